// round 14
// baseline (speedup 1.0000x reference)
#include <cuda_runtime.h>
#include <cuda_fp16.h>
#include <cstdint>

// y[m,n] = mask[m] ? x[m,:]·W_v[n,:] : x[m,:]·W_t[n,:]
// Mask-partitioned single GEMM, fp16 m16n8k16 mma.sync, fp32 accumulate.
// GEMM: R13 core (128x128 CTA, 4 warps @64x64, frag-order smem, 4-stage
// cp.async, 3 CTAs/SM, tail-correct waits). Prep: one-pass slot assign;
// k3 now converts TWO k-panels per block with 8 batched LDG.128 (MLP 8).

#define M_TOTAL 32768
#define K_DIM   1024
#define N_DIM   1024
#define BM 128
#define BN 128
#define BK 32
#define STAGES 4
#define NK (K_DIM / BK)              // 32 k-panels
#define THREADS 128
#define M_PAD 32896                  // 257 tiles * 128
#define NMT (M_PAD / BM)             // 257

#define PANEL_H  4096                // halves per 8KB panel
#define APANEL_B 8192
#define STAGE_B  16384               // A panel + B panel
#define DYN_SMEM (STAGES * STAGE_B)  // 64 KB

// ------------------------------------------------------------- device state
__device__ __half g_x[(size_t)M_PAD * K_DIM];    // [mtile][kpanel][frag order]
__device__ __half g_wv[(size_t)N_DIM * K_DIM];   // [ntile][kpanel][frag order]
__device__ __half g_wt[(size_t)N_DIM * K_DIM];
__device__ int   g_perm[M_PAD];                  // slot -> source row (live only)
__device__ int   g_cv, g_ct;
__device__ int   g_mask_is_u8;

// Slot map: visual -> [0, nv) ascending; dead gap [nv, nv+128);
// text -> [nv+128, M_PAD) descending. Tile t uses W_v iff 128*t < nv.

// ------------------------------------------------------------- helpers
__device__ __forceinline__ bool mask_at(const unsigned char* m, int i) {
    return g_mask_is_u8 ? (m[i] != 0) : (((const int*)m)[i] != 0);
}

__device__ __forceinline__ uint32_t smem_u32(const void* p) {
    uint32_t a;
    asm("{ .reg .u64 t; cvta.to.shared.u64 t, %1; cvt.u32.u64 %0, t; }"
        : "=r"(a) : "l"(p));
    return a;
}

__device__ __forceinline__ void cp16(uint32_t saddr, const void* g) {
    asm volatile("cp.async.cg.shared.global [%0], [%1], 16;"
                 :: "r"(saddr), "l"(g) : "memory");
}

__device__ __forceinline__ void mma_f16(float* d, const uint32_t* a, const uint32_t* b) {
    asm volatile(
        "mma.sync.aligned.m16n8k16.row.col.f32.f16.f16.f32 "
        "{%0,%1,%2,%3}, {%4,%5,%6,%7}, {%8,%9}, {%0,%1,%2,%3};"
        : "+f"(d[0]), "+f"(d[1]), "+f"(d[2]), "+f"(d[3])
        : "r"(a[0]), "r"(a[1]), "r"(a[2]), "r"(a[3]), "r"(b[0]), "r"(b[1]));
}

// ------------------------------------------------------------- prep kernels
__global__ void k0_init(const unsigned char* __restrict__ m) {
    __shared__ int found;
    int tid = threadIdx.x;
    if (tid == 0) { found = 0; g_cv = 0; g_ct = 0; }
    __syncthreads();
    int local = 0;
    for (int i = tid; i < 8192; i += 1024)
        if (m[4 * i + 1] | m[4 * i + 2] | m[4 * i + 3]) local = 1;
    if (local) atomicOr(&found, 1);
    __syncthreads();
    if (tid == 0) g_mask_is_u8 = found;
}

// K12: one-pass slot assignment (visual ascending, text descending).
__global__ void k12_assign(const unsigned char* __restrict__ m) {
    int tid = threadIdx.x;
    int row = blockIdx.x * 256 + tid;
    int lane = tid & 31;
    bool mv = mask_at(m, row);
    unsigned bal = __ballot_sync(0xffffffffu, mv);
    int cv = __popc(bal);
    int lpv = __popc(bal & ((1u << lane) - 1));
    int lpt = lane - lpv;
    int baseV = 0, baseT = 0;
    if (lane == 0) {
        baseV = atomicAdd(&g_cv, cv);
        baseT = atomicAdd(&g_ct, 32 - cv);
    }
    baseV = __shfl_sync(0xffffffffu, baseV, 0);
    baseT = __shfl_sync(0xffffffffu, baseT, 0);
    int slot = mv ? (baseV + lpv) : (M_PAD - 1 - (baseT + lpt));
    g_perm[slot] = row;
}

// K3: x gather + fp16 convert -> A panels. TWO k-panels per block:
// 8 batched LDG.128/thread (MLP 8), 256B contiguous per gathered row.
__global__ void k3_xconv(const float* __restrict__ x) {
    __shared__ float sx[BM * 64];     // 128 rows x 64 floats (2 panels worth)
    __shared__ int sperm[BM];
    const int mt = blockIdx.x, kp2 = blockIdx.y;  // kp2: 0..15
    const int tid = threadIdx.x;
    const int kbase = kp2 * 64;
    const int nv = g_cv;
    if (tid < BM) {
        int slot = mt * BM + tid;
        bool live = (slot < nv) || (slot >= nv + BM);
        sperm[tid] = live ? g_perm[slot] : -1;
    }
    __syncthreads();

    float4 v[8];
    #pragma unroll
    for (int i = 0; i < 8; i++) {
        int c = i * 256 + tid;            // 0..2047
        int row = c >> 4, q = c & 15;     // 16 x 16B chunks per row
        int src = sperm[row];
        v[i] = (src >= 0)
            ? *(const float4*)(x + (size_t)src * K_DIM + kbase + q * 4)
            : make_float4(0.f, 0.f, 0.f, 0.f);
    }
    #pragma unroll
    for (int i = 0; i < 8; i++) {
        int c = i * 256 + tid;
        int row = c >> 4, q = c & 15;
        *(float4*)(sx + row * 64 + q * 4) = v[i];
    }
    __syncthreads();

    #pragma unroll
    for (int p = 0; p < 2; p++) {
        __half* dst = g_x + ((size_t)mt * NK + kp2 * 2 + p) * PANEL_H;
        const int ko = p * 32;
        #pragma unroll
        for (int i = 0; i < 2; i++) {
            int h0 = (i * 256 + tid) * 8;
            int b = h0 >> 8;
            int rb = b >> 1, ks = b & 1;
            int lane = (h0 >> 3) & 31;
            int grp = lane >> 2, qid = lane & 3;
            __half vals[8];
            #pragma unroll
            for (int reg = 0; reg < 4; reg++) {
                int row = rb * 16 + grp + 8 * (reg & 1);
                int k   = ko + ks * 16 + 2 * qid + 8 * (reg >> 1);
                vals[reg * 2 + 0] = __float2half_rn(sx[row * 64 + k]);
                vals[reg * 2 + 1] = __float2half_rn(sx[row * 64 + k + 1]);
            }
            *(uint4*)(dst + h0) = *(const uint4*)vals;
        }
    }
}

// K4: weights -> fp16 B panels in fragment order (z selects matrix).
__global__ void k4_wconv(const float* __restrict__ Wv, const float* __restrict__ Wt) {
    const int nt = blockIdx.x, kp = blockIdx.y;
    const float* W = blockIdx.z ? Wt : Wv;
    __half* dst = (blockIdx.z ? g_wt : g_wv) + ((size_t)nt * NK + kp) * PANEL_H;
    const int tid = threadIdx.x;
    const int kbase = kp * BK;
    #pragma unroll
    for (int q = 0; q < 2; q++) {
        int h0 = tid * 8 + q * 2048;
        __half vals[8];
        #pragma unroll
        for (int j = 0; j < 8; j++) {
            int h = h0 + j;
            int blk = h >> 7;
            int nb = blk >> 1, ks = blk & 1;
            int lane = (h >> 2) & 31;
            int v = h & 3;
            int grp = lane >> 2, qid = lane & 3;
            int n = nt * 128 + nb * 8 + grp;
            int k = kbase + ks * 16 + 2 * qid + 8 * (v >> 1) + (v & 1);
            vals[j] = __float2half_rn(W[(size_t)n * K_DIM + k]);
        }
        *(uint4*)(dst + h0) = *(const uint4*)vals;
    }
}

// ------------------------------------------------------------- GEMM (R13 core)
extern __shared__ __align__(128) char dsmem[];

__global__ __launch_bounds__(THREADS, 3)
void gemm_kernel(float* __restrict__ out)
{
    const int tid  = threadIdx.x;
    const int warp = tid >> 5;
    const int lane = tid & 31;
    const int grp  = lane >> 2;
    const int qid  = lane & 3;
    const int rb0  = (warp >> 1) * 4;        // A block base (64 rows)
    const int nb0  = (warp & 1) * 8;         // B block base (64 cols)
    const int blockN = blockIdx.x * BN;
    const int mt     = blockIdx.y;
    const int blockM = mt * BM;

    const int nv = g_cv;
    const char* gA = (const char*)(g_x + (size_t)mt * NK * PANEL_H);
    const char* gB = (const char*)(((blockM < nv) ? g_wv : g_wt)
                                   + (size_t)blockIdx.x * NK * PANEL_H);

    const uint32_t sbase = smem_u32(dsmem);

    float acc[4][8][4];
    #pragma unroll
    for (int i = 0; i < 4; i++)
        #pragma unroll
        for (int j = 0; j < 8; j++)
            #pragma unroll
            for (int c = 0; c < 4; c++) acc[i][j][c] = 0.f;

    auto ISSUE = [&](int kt) {
        const uint32_t sst = sbase + (kt & (STAGES - 1)) * STAGE_B;
        const char* srcA = gA + (size_t)kt * APANEL_B;
        const char* srcB = gB + (size_t)kt * APANEL_B;
        #pragma unroll
        for (int i = 0; i < 4; i++) {
            uint32_t off = (uint32_t)(i * 2048 + tid * 16);
            cp16(sst + off, srcA + off);
        }
        #pragma unroll
        for (int i = 0; i < 4; i++) {
            uint32_t off = (uint32_t)(i * 2048 + tid * 16);
            cp16(sst + APANEL_B + off, srcB + off);
        }
        asm volatile("cp.async.commit_group;" ::: "memory");
    };

    ISSUE(0); ISSUE(1); ISSUE(2);

    for (int kt = 0; kt < NK; kt++) {
        // Tail-correct wait: group kt must be complete past this point.
        if (kt < NK - 2)
            asm volatile("cp.async.wait_group 2;" ::: "memory");
        else if (kt == NK - 2)
            asm volatile("cp.async.wait_group 1;" ::: "memory");
        else
            asm volatile("cp.async.wait_group 0;" ::: "memory");
        __syncthreads();
        if (kt + STAGES - 1 < NK) ISSUE(kt + STAGES - 1);

        const char* stage = dsmem + (kt & (STAGES - 1)) * STAGE_B;
        const char* sB = stage + APANEL_B;

        #pragma unroll
        for (int ks = 0; ks < 2; ks++) {
            uint32_t a[4][4];
            #pragma unroll
            for (int i = 0; i < 4; i++) {
                uint4 v = *(const uint4*)(stage + ((rb0 + i) * 2 + ks) * 512
                                          + lane * 16);
                a[i][0] = v.x; a[i][1] = v.y; a[i][2] = v.z; a[i][3] = v.w;
            }
            uint32_t b[8][2];
            #pragma unroll
            for (int j = 0; j < 8; j++) {
                uint2 v = *(const uint2*)(sB + ((nb0 + j) * 2 + ks) * 256 + lane * 8);
                b[j][0] = v.x; b[j][1] = v.y;
            }
            #pragma unroll
            for (int i = 0; i < 4; i++)
                #pragma unroll
                for (int j = 0; j < 8; j++)
                    mma_f16(acc[i][j], a[i], b[j]);
        }
    }

    // epilogue: scatter live rows through perm
    #pragma unroll
    for (int i = 0; i < 4; i++) {
        int r = (rb0 + i) * 16 + grp;
        int s0 = blockM + r, s1 = blockM + r + 8;
        int d0 = ((s0 < nv) || (s0 >= nv + BM)) ? g_perm[s0] : -1;
        int d1 = ((s1 < nv) || (s1 >= nv + BM)) ? g_perm[s1] : -1;
        #pragma unroll
        for (int j = 0; j < 8; j++) {
            int col = blockN + (nb0 + j) * 8 + qid * 2;
            if (d0 >= 0)
                *(float2*)(out + (size_t)d0 * N_DIM + col) =
                    make_float2(acc[i][j][0], acc[i][j][1]);
            if (d1 >= 0)
                *(float2*)(out + (size_t)d1 * N_DIM + col) =
                    make_float2(acc[i][j][2], acc[i][j][3]);
        }
    }
}

// ------------------------------------------------------------- launch
extern "C" void kernel_launch(void* const* d_in, const int* in_sizes, int n_in,
                              void* d_out, int out_size)
{
    const float*         x    = (const float*)d_in[0];
    const unsigned char* mask = (const unsigned char*)d_in[1];
    const float*         Wv   = (const float*)d_in[2];
    const float*         Wt   = (const float*)d_in[3];
    float*               out  = (float*)d_out;

    static bool attr_set = false;
    if (!attr_set) {
        cudaFuncSetAttribute(gemm_kernel,
                             cudaFuncAttributeMaxDynamicSharedMemorySize, DYN_SMEM);
        attr_set = true;
    }

    k0_init<<<1, 1024>>>(mask);
    k12_assign<<<M_TOTAL / 256, 256>>>(mask);
    k3_xconv<<<dim3(NMT, NK / 2), 256>>>(x);
    k4_wconv<<<dim3(N_DIM / 128, NK, 2), 256>>>(Wv, Wt);
    gemm_kernel<<<dim3(N_DIM / BN, NMT), THREADS, DYN_SMEM>>>(out);
}

// round 15
// speedup vs baseline: 1.0449x; 1.0449x over previous
#include <cuda_runtime.h>
#include <cuda_fp16.h>
#include <cstdint>

// y[m,n] = mask[m] ? x[m,:]·W_v[n,:] : x[m,:]·W_t[n,:]
// Mask-partitioned single GEMM, fp16 m16n8k16 mma.sync, fp32 accumulate.
// GEMM: R13 core (128x128 CTA, 4 warps @64x64, frag-order smem, 4-stage
// cp.async, 3 CTAs/SM, tail-correct waits) + B-pair packing: both B frags
// of a j-block pair in one LDS.128 (8 LDS.64 -> 4 LDS.128 per warp-ks).
// Prep: R13 k3 (single-panel, MLP-batched), pair-packed k4.

#define M_TOTAL 32768
#define K_DIM   1024
#define N_DIM   1024
#define BM 128
#define BN 128
#define BK 32
#define STAGES 4
#define NK (K_DIM / BK)              // 32 k-panels
#define THREADS 128
#define M_PAD 32896                  // 257 tiles * 128
#define NMT (M_PAD / BM)             // 257

#define PANEL_H  4096                // halves per 8KB panel
#define APANEL_B 8192
#define STAGE_B  16384               // A panel + B panel
#define DYN_SMEM (STAGES * STAGE_B)  // 64 KB

// ------------------------------------------------------------- device state
__device__ __half g_x[(size_t)M_PAD * K_DIM];    // [mtile][kpanel][frag order]
__device__ __half g_wv[(size_t)N_DIM * K_DIM];   // [ntile][kpanel][pair-packed]
__device__ __half g_wt[(size_t)N_DIM * K_DIM];
__device__ int   g_perm[M_PAD];                  // slot -> source row (live only)
__device__ int   g_cv, g_ct;
__device__ int   g_mask_is_u8;

// Slot map: visual -> [0, nv) ascending; dead gap [nv, nv+128);
// text -> [nv+128, M_PAD) descending. Tile t uses W_v iff 128*t < nv.

// ------------------------------------------------------------- helpers
__device__ __forceinline__ bool mask_at(const unsigned char* m, int i) {
    return g_mask_is_u8 ? (m[i] != 0) : (((const int*)m)[i] != 0);
}

__device__ __forceinline__ uint32_t smem_u32(const void* p) {
    uint32_t a;
    asm("{ .reg .u64 t; cvta.to.shared.u64 t, %1; cvt.u32.u64 %0, t; }"
        : "=r"(a) : "l"(p));
    return a;
}

__device__ __forceinline__ void cp16(uint32_t saddr, const void* g) {
    asm volatile("cp.async.cg.shared.global [%0], [%1], 16;"
                 :: "r"(saddr), "l"(g) : "memory");
}

__device__ __forceinline__ void mma_f16(float* d, const uint32_t* a, const uint32_t* b) {
    asm volatile(
        "mma.sync.aligned.m16n8k16.row.col.f32.f16.f16.f32 "
        "{%0,%1,%2,%3}, {%4,%5,%6,%7}, {%8,%9}, {%0,%1,%2,%3};"
        : "+f"(d[0]), "+f"(d[1]), "+f"(d[2]), "+f"(d[3])
        : "r"(a[0]), "r"(a[1]), "r"(a[2]), "r"(a[3]), "r"(b[0]), "r"(b[1]));
}

// ------------------------------------------------------------- prep kernels
__global__ void k0_init(const unsigned char* __restrict__ m) {
    __shared__ int found;
    int tid = threadIdx.x;
    if (tid == 0) { found = 0; g_cv = 0; g_ct = 0; }
    __syncthreads();
    int local = 0;
    for (int i = tid; i < 8192; i += 1024)
        if (m[4 * i + 1] | m[4 * i + 2] | m[4 * i + 3]) local = 1;
    if (local) atomicOr(&found, 1);
    __syncthreads();
    if (tid == 0) g_mask_is_u8 = found;
}

// K12: one-pass slot assignment (visual ascending, text descending).
__global__ void k12_assign(const unsigned char* __restrict__ m) {
    int tid = threadIdx.x;
    int row = blockIdx.x * 256 + tid;
    int lane = tid & 31;
    bool mv = mask_at(m, row);
    unsigned bal = __ballot_sync(0xffffffffu, mv);
    int cv = __popc(bal);
    int lpv = __popc(bal & ((1u << lane) - 1));
    int lpt = lane - lpv;
    int baseV = 0, baseT = 0;
    if (lane == 0) {
        baseV = atomicAdd(&g_cv, cv);
        baseT = atomicAdd(&g_ct, 32 - cv);
    }
    baseV = __shfl_sync(0xffffffffu, baseV, 0);
    baseT = __shfl_sync(0xffffffffu, baseT, 0);
    int slot = mv ? (baseV + lpv) : (M_PAD - 1 - (baseT + lpt));
    g_perm[slot] = row;
}

// K3: x gather + fp16 convert -> A panels in fragment order (R13 version).
__global__ void k3_xconv(const float* __restrict__ x) {
    __shared__ float sx[BM * BK];
    __shared__ int sperm[BM];
    const int mt = blockIdx.x, kp = blockIdx.y;
    const int tid = threadIdx.x;
    const int kbase = kp * BK;
    const int nv = g_cv;
    if (tid < BM) {
        int slot = mt * BM + tid;
        bool live = (slot < nv) || (slot >= nv + BM);
        sperm[tid] = live ? g_perm[slot] : -1;
    }
    __syncthreads();

    float4 v[4];
    #pragma unroll
    for (int i = 0; i < 4; i++) {
        int idx = i * 256 + tid;          // 0..1023
        int row = idx >> 3, q = idx & 7;
        int src = sperm[row];
        v[i] = (src >= 0)
            ? *(const float4*)(x + (size_t)src * K_DIM + kbase + q * 4)
            : make_float4(0.f, 0.f, 0.f, 0.f);
    }
    #pragma unroll
    for (int i = 0; i < 4; i++) {
        int idx = i * 256 + tid;
        int row = idx >> 3, q = idx & 7;
        *(float4*)(sx + row * BK + q * 4) = v[i];
    }
    __syncthreads();

    __half* dst = g_x + ((size_t)mt * NK + kp) * PANEL_H;
    #pragma unroll
    for (int i = 0; i < 2; i++) {
        int h0 = (i * 256 + tid) * 8;
        int b = h0 >> 8;
        int rb = b >> 1, ks = b & 1;
        int lane = (h0 >> 3) & 31;
        int grp = lane >> 2, qid = lane & 3;
        __half vals[8];
        #pragma unroll
        for (int reg = 0; reg < 4; reg++) {
            int row = rb * 16 + grp + 8 * (reg & 1);
            int k   = ks * 16 + 2 * qid + 8 * (reg >> 1);
            vals[reg * 2 + 0] = __float2half_rn(sx[row * BK + k]);
            vals[reg * 2 + 1] = __float2half_rn(sx[row * BK + k + 1]);
        }
        *(uint4*)(dst + h0) = *(const uint4*)vals;
    }
}

// K4: weights -> fp16 B panels, PAIR-PACKED:
// halves h = (pair*2+ks)*256 + lane*8 + v, v in 0..7:
//   j = 2*pair + (v>>2), vv = v&3
//   n = j*8 + grp, k = ks*16 + 2*qid + 8*(vv>>1) + (vv&1)
__global__ void k4_wconv(const float* __restrict__ Wv, const float* __restrict__ Wt) {
    const int nt = blockIdx.x, kp = blockIdx.y;
    const float* W = blockIdx.z ? Wt : Wv;
    __half* dst = (blockIdx.z ? g_wt : g_wv) + ((size_t)nt * NK + kp) * PANEL_H;
    const int tid = threadIdx.x;
    const int kbase = kp * BK;
    #pragma unroll
    for (int q = 0; q < 2; q++) {
        int h0 = tid * 8 + q * 2048;
        int blk = h0 >> 8;                 // pair*2 + ks
        int pair = blk >> 1, ks = blk & 1;
        int lane = (h0 >> 3) & 31;
        int grp = lane >> 2, qid = lane & 3;
        __half vals[8];
        #pragma unroll
        for (int v = 0; v < 8; v++) {
            int j  = 2 * pair + (v >> 2);
            int vv = v & 3;
            int n = nt * 128 + j * 8 + grp;
            int k = kbase + ks * 16 + 2 * qid + 8 * (vv >> 1) + (vv & 1);
            vals[v] = __float2half_rn(W[(size_t)n * K_DIM + k]);
        }
        *(uint4*)(dst + h0) = *(const uint4*)vals;
    }
}

// ------------------------------------------------------------- GEMM (R13 core + B pairs)
extern __shared__ __align__(128) char dsmem[];

__global__ __launch_bounds__(THREADS, 3)
void gemm_kernel(float* __restrict__ out)
{
    const int tid  = threadIdx.x;
    const int warp = tid >> 5;
    const int lane = tid & 31;
    const int grp  = lane >> 2;
    const int qid  = lane & 3;
    const int rb0  = (warp >> 1) * 4;        // A block base (64 rows)
    const int nb0  = (warp & 1) * 8;         // B block base (64 cols)
    const int pb0  = nb0 >> 1;               // B pair base (4 pairs)
    const int blockN = blockIdx.x * BN;
    const int mt     = blockIdx.y;
    const int blockM = mt * BM;

    const int nv = g_cv;
    const char* gA = (const char*)(g_x + (size_t)mt * NK * PANEL_H);
    const char* gB = (const char*)(((blockM < nv) ? g_wv : g_wt)
                                   + (size_t)blockIdx.x * NK * PANEL_H);

    const uint32_t sbase = smem_u32(dsmem);

    float acc[4][8][4];
    #pragma unroll
    for (int i = 0; i < 4; i++)
        #pragma unroll
        for (int j = 0; j < 8; j++)
            #pragma unroll
            for (int c = 0; c < 4; c++) acc[i][j][c] = 0.f;

    auto ISSUE = [&](int kt) {
        const uint32_t sst = sbase + (kt & (STAGES - 1)) * STAGE_B;
        const char* srcA = gA + (size_t)kt * APANEL_B;
        const char* srcB = gB + (size_t)kt * APANEL_B;
        #pragma unroll
        for (int i = 0; i < 4; i++) {
            uint32_t off = (uint32_t)(i * 2048 + tid * 16);
            cp16(sst + off, srcA + off);
        }
        #pragma unroll
        for (int i = 0; i < 4; i++) {
            uint32_t off = (uint32_t)(i * 2048 + tid * 16);
            cp16(sst + APANEL_B + off, srcB + off);
        }
        asm volatile("cp.async.commit_group;" ::: "memory");
    };

    ISSUE(0); ISSUE(1); ISSUE(2);

    for (int kt = 0; kt < NK; kt++) {
        // Tail-correct wait: group kt must be complete past this point.
        if (kt < NK - 2)
            asm volatile("cp.async.wait_group 2;" ::: "memory");
        else if (kt == NK - 2)
            asm volatile("cp.async.wait_group 1;" ::: "memory");
        else
            asm volatile("cp.async.wait_group 0;" ::: "memory");
        __syncthreads();
        if (kt + STAGES - 1 < NK) ISSUE(kt + STAGES - 1);

        const char* stage = dsmem + (kt & (STAGES - 1)) * STAGE_B;
        const char* sB = stage + APANEL_B;

        #pragma unroll
        for (int ks = 0; ks < 2; ks++) {
            uint32_t a[4][4];
            #pragma unroll
            for (int i = 0; i < 4; i++) {
                uint4 v = *(const uint4*)(stage + ((rb0 + i) * 2 + ks) * 512
                                          + lane * 16);
                a[i][0] = v.x; a[i][1] = v.y; a[i][2] = v.z; a[i][3] = v.w;
            }
            uint32_t b[8][2];
            #pragma unroll
            for (int jp = 0; jp < 4; jp++) {
                uint4 v = *(const uint4*)(sB + ((pb0 + jp) * 2 + ks) * 512
                                          + lane * 16);
                b[2 * jp][0] = v.x;     b[2 * jp][1] = v.y;
                b[2 * jp + 1][0] = v.z; b[2 * jp + 1][1] = v.w;
            }
            #pragma unroll
            for (int i = 0; i < 4; i++)
                #pragma unroll
                for (int j = 0; j < 8; j++)
                    mma_f16(acc[i][j], a[i], b[j]);
        }
    }

    // epilogue: scatter live rows through perm
    #pragma unroll
    for (int i = 0; i < 4; i++) {
        int r = (rb0 + i) * 16 + grp;
        int s0 = blockM + r, s1 = blockM + r + 8;
        int d0 = ((s0 < nv) || (s0 >= nv + BM)) ? g_perm[s0] : -1;
        int d1 = ((s1 < nv) || (s1 >= nv + BM)) ? g_perm[s1] : -1;
        #pragma unroll
        for (int j = 0; j < 8; j++) {
            int col = blockN + (nb0 + j) * 8 + qid * 2;
            if (d0 >= 0)
                *(float2*)(out + (size_t)d0 * N_DIM + col) =
                    make_float2(acc[i][j][0], acc[i][j][1]);
            if (d1 >= 0)
                *(float2*)(out + (size_t)d1 * N_DIM + col) =
                    make_float2(acc[i][j][2], acc[i][j][3]);
        }
    }
}

// ------------------------------------------------------------- launch
extern "C" void kernel_launch(void* const* d_in, const int* in_sizes, int n_in,
                              void* d_out, int out_size)
{
    const float*         x    = (const float*)d_in[0];
    const unsigned char* mask = (const unsigned char*)d_in[1];
    const float*         Wv   = (const float*)d_in[2];
    const float*         Wt   = (const float*)d_in[3];
    float*               out  = (float*)d_out;

    static bool attr_set = false;
    if (!attr_set) {
        cudaFuncSetAttribute(gemm_kernel,
                             cudaFuncAttributeMaxDynamicSharedMemorySize, DYN_SMEM);
        attr_set = true;
    }

    k0_init<<<1, 1024>>>(mask);
    k12_assign<<<M_TOTAL / 256, 256>>>(mask);
    k3_xconv<<<dim3(NMT, NK), 256>>>(x);
    k4_wconv<<<dim3(N_DIM / 128, NK, 2), 256>>>(Wv, Wt);
    gemm_kernel<<<dim3(N_DIM / BN, NMT), THREADS, DYN_SMEM>>>(out);
}

// round 16
// speedup vs baseline: 1.0769x; 1.0307x over previous
#include <cuda_runtime.h>
#include <cuda_fp16.h>
#include <cstdint>

// y[m,n] = mask[m] ? x[m,:]·W_v[n,:] : x[m,:]·W_t[n,:]
// Mask-partitioned single GEMM, fp16 m16n8k16 mma.sync, fp32 accumulate.
// GEMM: R15 core, byte-identical (128x128 CTA, 4 warps @64x64, frag-order
// smem, B-pair packing, 4-stage cp.async, 3 CTAs/SM, tail-correct waits).
// Prep collapsed to 2 launches: k12 (slot assign w/ inline dtype probe),
// k34 (x-convert blocks + W-convert blocks in one grid, overlapped).

#define M_TOTAL 32768
#define K_DIM   1024
#define N_DIM   1024
#define BM 128
#define BN 128
#define BK 32
#define STAGES 4
#define NK (K_DIM / BK)              // 32 k-panels
#define THREADS 128
#define M_PAD 32896                  // 257 tiles * 128
#define NMT (M_PAD / BM)             // 257

#define PANEL_H  4096                // halves per 8KB panel
#define APANEL_B 8192
#define STAGE_B  16384               // A panel + B panel
#define DYN_SMEM (STAGES * STAGE_B)  // 64 KB

// ------------------------------------------------------------- device state
__device__ __half g_x[(size_t)M_PAD * K_DIM];    // [mtile][kpanel][frag order]
__device__ __half g_wv[(size_t)N_DIM * K_DIM];   // [ntile][kpanel][pair-packed]
__device__ __half g_wt[(size_t)N_DIM * K_DIM];
__device__ int   g_perm[M_PAD];                  // slot -> source row (live only)
__device__ int   g_cv, g_ct;

// Slot map: visual -> [0, nv) ascending; dead gap [nv, nv+128);
// text -> [nv+128, M_PAD) descending. Tile t uses W_v iff 128*t < nv.

// ------------------------------------------------------------- helpers
__device__ __forceinline__ uint32_t smem_u32(const void* p) {
    uint32_t a;
    asm("{ .reg .u64 t; cvta.to.shared.u64 t, %1; cvt.u32.u64 %0, t; }"
        : "=r"(a) : "l"(p));
    return a;
}

__device__ __forceinline__ void cp16(uint32_t saddr, const void* g) {
    asm volatile("cp.async.cg.shared.global [%0], [%1], 16;"
                 :: "r"(saddr), "l"(g) : "memory");
}

__device__ __forceinline__ void mma_f16(float* d, const uint32_t* a, const uint32_t* b) {
    asm volatile(
        "mma.sync.aligned.m16n8k16.row.col.f32.f16.f16.f32 "
        "{%0,%1,%2,%3}, {%4,%5,%6,%7}, {%8,%9}, {%0,%1,%2,%3};"
        : "+f"(d[0]), "+f"(d[1]), "+f"(d[2]), "+f"(d[3])
        : "r"(a[0]), "r"(a[1]), "r"(a[2]), "r"(a[3]), "r"(b[0]), "r"(b[1]));
}

// ------------------------------------------------------------- prep kernels
// K12: init counters (block 0 not needed — atomics start from memset? no:
// we zero g_cv/g_ct via a tiny grid-stride trick: every block CAS-free —
// instead, counters are zeroed by gemm's previous run? NOT deterministic.
// Solution: dedicated zeroing by first scheduled block is racy; use
// a separate tiny kernel-free approach: zero them in k12 via block 0 is
// racy too. So: zero via cudaMemsetAsync in kernel_launch (graph-legal,
// device-to-device constant fill, no alloc).
//
// Slot assignment with inline mask-dtype probe (per-block, no global flag):
// int32 0/1 data has zero bytes at offsets 4i+1..3; u8 random bools don't.
__global__ void k12_assign(const unsigned char* __restrict__ m) {
    int tid = threadIdx.x;
    int probe = 0;
    if (tid < 256) {
        if (m[4 * tid + 1] | m[4 * tid + 2] | m[4 * tid + 3]) probe = 1;
    }
    int is_u8 = __syncthreads_or(probe);

    int row = blockIdx.x * 256 + tid;
    int lane = tid & 31;
    bool mv = is_u8 ? (m[row] != 0) : (((const int*)m)[row] != 0);
    unsigned bal = __ballot_sync(0xffffffffu, mv);
    int cv = __popc(bal);
    int lpv = __popc(bal & ((1u << lane) - 1));
    int lpt = lane - lpv;
    int baseV = 0, baseT = 0;
    if (lane == 0) {
        baseV = atomicAdd(&g_cv, cv);
        baseT = atomicAdd(&g_ct, 32 - cv);
    }
    baseV = __shfl_sync(0xffffffffu, baseV, 0);
    baseT = __shfl_sync(0xffffffffu, baseT, 0);
    int slot = mv ? (baseV + lpv) : (M_PAD - 1 - (baseT + lpt));
    g_perm[slot] = row;
}

// K34: merged conversion grid. blockIdx.x < NMT: x gather+convert (panel
// mt=bx, kp=by). blockIdx.x >= NMT: weight convert (16 blocks: which/nt).
__global__ void k34_conv(const float* __restrict__ x,
                         const float* __restrict__ Wv,
                         const float* __restrict__ Wt)
{
    const int bx = blockIdx.x, kp = blockIdx.y;
    const int tid = threadIdx.x;
    const int kbase = kp * BK;

    if (bx >= NMT) {
        // ---- weight path: pair-packed B panels ----
        int b = bx - NMT;                   // 0..15
        int which = b >> 3, nt = b & 7;
        const float* W = which ? Wt : Wv;
        __half* dst = (which ? g_wt : g_wv) + ((size_t)nt * NK + kp) * PANEL_H;
        #pragma unroll
        for (int q = 0; q < 2; q++) {
            int h0 = tid * 8 + q * 2048;
            int blk = h0 >> 8;              // pair*2 + ks
            int pair = blk >> 1, ks = blk & 1;
            int lane = (h0 >> 3) & 31;
            int grp = lane >> 2, qid = lane & 3;
            __half vals[8];
            #pragma unroll
            for (int v = 0; v < 8; v++) {
                int j  = 2 * pair + (v >> 2);
                int vv = v & 3;
                int n = nt * 128 + j * 8 + grp;
                int k = kbase + ks * 16 + 2 * qid + 8 * (vv >> 1) + (vv & 1);
                vals[v] = __float2half_rn(W[(size_t)n * K_DIM + k]);
            }
            *(uint4*)(dst + h0) = *(const uint4*)vals;
        }
        return;
    }

    // ---- x path: gather + fp16 convert -> A panel (frag order) ----
    __shared__ float sx[BM * BK];
    __shared__ int sperm[BM];
    const int mt = bx;
    const int nv = g_cv;
    if (tid < BM) {
        int slot = mt * BM + tid;
        bool live = (slot < nv) || (slot >= nv + BM);
        sperm[tid] = live ? g_perm[slot] : -1;
    }
    __syncthreads();

    float4 v[4];
    #pragma unroll
    for (int i = 0; i < 4; i++) {
        int idx = i * 256 + tid;          // 0..1023
        int row = idx >> 3, q = idx & 7;
        int src = sperm[row];
        v[i] = (src >= 0)
            ? *(const float4*)(x + (size_t)src * K_DIM + kbase + q * 4)
            : make_float4(0.f, 0.f, 0.f, 0.f);
    }
    #pragma unroll
    for (int i = 0; i < 4; i++) {
        int idx = i * 256 + tid;
        int row = idx >> 3, q = idx & 7;
        *(float4*)(sx + row * BK + q * 4) = v[i];
    }
    __syncthreads();

    __half* dst = g_x + ((size_t)mt * NK + kp) * PANEL_H;
    #pragma unroll
    for (int i = 0; i < 2; i++) {
        int h0 = (i * 256 + tid) * 8;
        int b = h0 >> 8;
        int rb = b >> 1, ks = b & 1;
        int lane = (h0 >> 3) & 31;
        int grp = lane >> 2, qid = lane & 3;
        __half vals[8];
        #pragma unroll
        for (int reg = 0; reg < 4; reg++) {
            int row = rb * 16 + grp + 8 * (reg & 1);
            int k   = ks * 16 + 2 * qid + 8 * (reg >> 1);
            vals[reg * 2 + 0] = __float2half_rn(sx[row * BK + k]);
            vals[reg * 2 + 1] = __float2half_rn(sx[row * BK + k + 1]);
        }
        *(uint4*)(dst + h0) = *(const uint4*)vals;
    }
}

// ------------------------------------------------------------- GEMM (R15 core)
extern __shared__ __align__(128) char dsmem[];

__global__ __launch_bounds__(THREADS, 3)
void gemm_kernel(float* __restrict__ out)
{
    const int tid  = threadIdx.x;
    const int warp = tid >> 5;
    const int lane = tid & 31;
    const int grp  = lane >> 2;
    const int qid  = lane & 3;
    const int rb0  = (warp >> 1) * 4;        // A block base (64 rows)
    const int nb0  = (warp & 1) * 8;         // B block base (64 cols)
    const int pb0  = nb0 >> 1;               // B pair base (4 pairs)
    const int blockN = blockIdx.x * BN;
    const int mt     = blockIdx.y;
    const int blockM = mt * BM;

    const int nv = g_cv;
    const char* gA = (const char*)(g_x + (size_t)mt * NK * PANEL_H);
    const char* gB = (const char*)(((blockM < nv) ? g_wv : g_wt)
                                   + (size_t)blockIdx.x * NK * PANEL_H);

    const uint32_t sbase = smem_u32(dsmem);

    float acc[4][8][4];
    #pragma unroll
    for (int i = 0; i < 4; i++)
        #pragma unroll
        for (int j = 0; j < 8; j++)
            #pragma unroll
            for (int c = 0; c < 4; c++) acc[i][j][c] = 0.f;

    auto ISSUE = [&](int kt) {
        const uint32_t sst = sbase + (kt & (STAGES - 1)) * STAGE_B;
        const char* srcA = gA + (size_t)kt * APANEL_B;
        const char* srcB = gB + (size_t)kt * APANEL_B;
        #pragma unroll
        for (int i = 0; i < 4; i++) {
            uint32_t off = (uint32_t)(i * 2048 + tid * 16);
            cp16(sst + off, srcA + off);
        }
        #pragma unroll
        for (int i = 0; i < 4; i++) {
            uint32_t off = (uint32_t)(i * 2048 + tid * 16);
            cp16(sst + APANEL_B + off, srcB + off);
        }
        asm volatile("cp.async.commit_group;" ::: "memory");
    };

    ISSUE(0); ISSUE(1); ISSUE(2);

    for (int kt = 0; kt < NK; kt++) {
        // Tail-correct wait: group kt must be complete past this point.
        if (kt < NK - 2)
            asm volatile("cp.async.wait_group 2;" ::: "memory");
        else if (kt == NK - 2)
            asm volatile("cp.async.wait_group 1;" ::: "memory");
        else
            asm volatile("cp.async.wait_group 0;" ::: "memory");
        __syncthreads();
        if (kt + STAGES - 1 < NK) ISSUE(kt + STAGES - 1);

        const char* stage = dsmem + (kt & (STAGES - 1)) * STAGE_B;
        const char* sB = stage + APANEL_B;

        #pragma unroll
        for (int ks = 0; ks < 2; ks++) {
            uint32_t a[4][4];
            #pragma unroll
            for (int i = 0; i < 4; i++) {
                uint4 v = *(const uint4*)(stage + ((rb0 + i) * 2 + ks) * 512
                                          + lane * 16);
                a[i][0] = v.x; a[i][1] = v.y; a[i][2] = v.z; a[i][3] = v.w;
            }
            uint32_t b[8][2];
            #pragma unroll
            for (int jp = 0; jp < 4; jp++) {
                uint4 v = *(const uint4*)(sB + ((pb0 + jp) * 2 + ks) * 512
                                          + lane * 16);
                b[2 * jp][0] = v.x;     b[2 * jp][1] = v.y;
                b[2 * jp + 1][0] = v.z; b[2 * jp + 1][1] = v.w;
            }
            #pragma unroll
            for (int i = 0; i < 4; i++)
                #pragma unroll
                for (int j = 0; j < 8; j++)
                    mma_f16(acc[i][j], a[i], b[j]);
        }
    }

    // epilogue: scatter live rows through perm
    #pragma unroll
    for (int i = 0; i < 4; i++) {
        int r = (rb0 + i) * 16 + grp;
        int s0 = blockM + r, s1 = blockM + r + 8;
        int d0 = ((s0 < nv) || (s0 >= nv + BM)) ? g_perm[s0] : -1;
        int d1 = ((s1 < nv) || (s1 >= nv + BM)) ? g_perm[s1] : -1;
        #pragma unroll
        for (int j = 0; j < 8; j++) {
            int col = blockN + (nb0 + j) * 8 + qid * 2;
            if (d0 >= 0)
                *(float2*)(out + (size_t)d0 * N_DIM + col) =
                    make_float2(acc[i][j][0], acc[i][j][1]);
            if (d1 >= 0)
                *(float2*)(out + (size_t)d1 * N_DIM + col) =
                    make_float2(acc[i][j][2], acc[i][j][3]);
        }
    }
}

// ------------------------------------------------------------- launch
extern "C" void kernel_launch(void* const* d_in, const int* in_sizes, int n_in,
                              void* d_out, int out_size)
{
    const float*         x    = (const float*)d_in[0];
    const unsigned char* mask = (const unsigned char*)d_in[1];
    const float*         Wv   = (const float*)d_in[2];
    const float*         Wt   = (const float*)d_in[3];
    float*               out  = (float*)d_out;

    static bool attr_set = false;
    if (!attr_set) {
        cudaFuncSetAttribute(gemm_kernel,
                             cudaFuncAttributeMaxDynamicSharedMemorySize, DYN_SMEM);
        attr_set = true;
    }

    // zero the slot counters (graph-capturable, no allocation)
    int* cv_addr = nullptr;
    cudaGetSymbolAddress((void**)&cv_addr, g_cv);
    cudaMemsetAsync(cv_addr, 0, sizeof(int));
    int* ct_addr = nullptr;
    cudaGetSymbolAddress((void**)&ct_addr, g_ct);
    cudaMemsetAsync(ct_addr, 0, sizeof(int));

    k12_assign<<<M_TOTAL / 256, 256>>>(mask);
    k34_conv<<<dim3(NMT + 16, NK), 256>>>(x, Wv, Wt);
    gemm_kernel<<<dim3(N_DIM / BN, NMT), THREADS, DYN_SMEM>>>(out);
}

// round 17
// speedup vs baseline: 1.0806x; 1.0035x over previous
#include <cuda_runtime.h>
#include <cuda_fp16.h>
#include <cstdint>

// y[m,n] = mask[m] ? x[m,:]·W_v[n,:] : x[m,:]·W_t[n,:]
// Mask-partitioned single GEMM, fp16 m16n8k16 mma.sync, fp32 accumulate.
// GEMM: R15/R16 core, byte-identical (128x128 CTA, 4 warps @64x64,
// frag-order smem, B-pair packing, 4-stage cp.async, 3 CTAs/SM,
// tail-correct waits). Prep: k12 = slot assign (block-aggregated atomics)
// + W-convert blocks fused into the same grid; k34 = pure x-convert.

#define M_TOTAL 32768
#define K_DIM   1024
#define N_DIM   1024
#define BM 128
#define BN 128
#define BK 32
#define STAGES 4
#define NK (K_DIM / BK)              // 32 k-panels
#define THREADS 128
#define M_PAD 32896                  // 257 tiles * 128
#define NMT (M_PAD / BM)             // 257

#define PANEL_H  4096                // halves per 8KB panel
#define APANEL_B 8192
#define STAGE_B  16384               // A panel + B panel
#define DYN_SMEM (STAGES * STAGE_B)  // 64 KB

#define MASK_BLOCKS (M_TOTAL / 256)  // 128
#define W_BLOCKS    512              // 2 matrices x 8 ntiles x 32 kpanels

// ------------------------------------------------------------- device state
__device__ __half g_x[(size_t)M_PAD * K_DIM];    // [mtile][kpanel][frag order]
__device__ __half g_wv[(size_t)N_DIM * K_DIM];   // [ntile][kpanel][pair-packed]
__device__ __half g_wt[(size_t)N_DIM * K_DIM];
__device__ int   g_perm[M_PAD];                  // slot -> source row (live only)
__device__ int   g_cv, g_ct;

// Slot map: visual -> [0, nv) ascending; dead gap [nv, nv+128);
// text -> [nv+128, M_PAD) descending. Tile t uses W_v iff 128*t < nv.

// ------------------------------------------------------------- helpers
__device__ __forceinline__ uint32_t smem_u32(const void* p) {
    uint32_t a;
    asm("{ .reg .u64 t; cvta.to.shared.u64 t, %1; cvt.u32.u64 %0, t; }"
        : "=r"(a) : "l"(p));
    return a;
}

__device__ __forceinline__ void cp16(uint32_t saddr, const void* g) {
    asm volatile("cp.async.cg.shared.global [%0], [%1], 16;"
                 :: "r"(saddr), "l"(g) : "memory");
}

__device__ __forceinline__ void mma_f16(float* d, const uint32_t* a, const uint32_t* b) {
    asm volatile(
        "mma.sync.aligned.m16n8k16.row.col.f32.f16.f16.f32 "
        "{%0,%1,%2,%3}, {%4,%5,%6,%7}, {%8,%9}, {%0,%1,%2,%3};"
        : "+f"(d[0]), "+f"(d[1]), "+f"(d[2]), "+f"(d[3])
        : "r"(a[0]), "r"(a[1]), "r"(a[2]), "r"(a[3]), "r"(b[0]), "r"(b[1]));
}

// ------------------------------------------------------------- prep kernels
// K12: merged grid.
//   bx < MASK_BLOCKS: slot assignment (inline dtype probe, block-aggregated
//     atomics: 2 atomicAdds per BLOCK instead of per warp).
//   bx >= MASK_BLOCKS: W-convert (pair-packed B panels) — mask-independent,
//     overlaps the assign path in the same launch.
__global__ void k12_assign_w(const unsigned char* __restrict__ m,
                             const float* __restrict__ Wv,
                             const float* __restrict__ Wt)
{
    const int tid = threadIdx.x;

    if (blockIdx.x >= MASK_BLOCKS) {
        // ---- W path ----
        int b = blockIdx.x - MASK_BLOCKS;       // 0..511
        int which = b >> 8;                     // 0/1
        int nt = (b >> 5) & 7;                  // 0..7
        int kp = b & 31;                        // 0..31
        const float* W = which ? Wt : Wv;
        __half* dst = (which ? g_wt : g_wv) + ((size_t)nt * NK + kp) * PANEL_H;
        const int kbase = kp * BK;
        #pragma unroll
        for (int q = 0; q < 2; q++) {
            int h0 = tid * 8 + q * 2048;
            int blk = h0 >> 8;                  // pair*2 + ks
            int pair = blk >> 1, ks = blk & 1;
            int lane = (h0 >> 3) & 31;
            int grp = lane >> 2, qid = lane & 3;
            __half vals[8];
            #pragma unroll
            for (int v = 0; v < 8; v++) {
                int j  = 2 * pair + (v >> 2);
                int vv = v & 3;
                int n = nt * 128 + j * 8 + grp;
                int k = kbase + ks * 16 + 2 * qid + 8 * (vv >> 1) + (vv & 1);
                vals[v] = __float2half_rn(W[(size_t)n * K_DIM + k]);
            }
            *(uint4*)(dst + h0) = *(const uint4*)vals;
        }
        return;
    }

    // ---- mask path ----
    __shared__ int s_v[8], s_t[8];
    __shared__ int s_baseV, s_baseT;

    int probe = 0;
    if (m[4 * tid + 1] | m[4 * tid + 2] | m[4 * tid + 3]) probe = 1;
    int is_u8 = __syncthreads_or(probe);

    int row = blockIdx.x * 256 + tid;
    int warp = tid >> 5, lane = tid & 31;
    bool mv = is_u8 ? (m[row] != 0) : (((const int*)m)[row] != 0);
    unsigned bal = __ballot_sync(0xffffffffu, mv);
    int wcv = __popc(bal);
    int lpv = __popc(bal & ((1u << lane) - 1));
    int lpt = lane - lpv;
    if (lane == 0) { s_v[warp] = wcv; s_t[warp] = 32 - wcv; }
    __syncthreads();
    if (tid == 0) {
        int av = 0, at = 0;
        #pragma unroll
        for (int w = 0; w < 8; w++) {
            int tv = s_v[w]; s_v[w] = av; av += tv;
            int tt = s_t[w]; s_t[w] = at; at += tt;
        }
        s_baseV = atomicAdd(&g_cv, av);
        s_baseT = atomicAdd(&g_ct, at);
    }
    __syncthreads();
    int slot = mv ? (s_baseV + s_v[warp] + lpv)
                  : (M_PAD - 1 - (s_baseT + s_t[warp] + lpt));
    g_perm[slot] = row;
}

// K34: pure x gather + fp16 convert -> A panels (frag order, MLP-batched).
__global__ void k34_xconv(const float* __restrict__ x)
{
    __shared__ float sx[BM * BK];
    __shared__ int sperm[BM];
    const int mt = blockIdx.x, kp = blockIdx.y;
    const int tid = threadIdx.x;
    const int kbase = kp * BK;
    const int nv = g_cv;
    if (tid < BM) {
        int slot = mt * BM + tid;
        bool live = (slot < nv) || (slot >= nv + BM);
        sperm[tid] = live ? g_perm[slot] : -1;
    }
    __syncthreads();

    float4 v[4];
    #pragma unroll
    for (int i = 0; i < 4; i++) {
        int idx = i * 256 + tid;          // 0..1023
        int row = idx >> 3, q = idx & 7;
        int src = sperm[row];
        v[i] = (src >= 0)
            ? *(const float4*)(x + (size_t)src * K_DIM + kbase + q * 4)
            : make_float4(0.f, 0.f, 0.f, 0.f);
    }
    #pragma unroll
    for (int i = 0; i < 4; i++) {
        int idx = i * 256 + tid;
        int row = idx >> 3, q = idx & 7;
        *(float4*)(sx + row * BK + q * 4) = v[i];
    }
    __syncthreads();

    __half* dst = g_x + ((size_t)mt * NK + kp) * PANEL_H;
    #pragma unroll
    for (int i = 0; i < 2; i++) {
        int h0 = (i * 256 + tid) * 8;
        int b = h0 >> 8;
        int rb = b >> 1, ks = b & 1;
        int lane = (h0 >> 3) & 31;
        int grp = lane >> 2, qid = lane & 3;
        __half vals[8];
        #pragma unroll
        for (int reg = 0; reg < 4; reg++) {
            int row = rb * 16 + grp + 8 * (reg & 1);
            int k   = ks * 16 + 2 * qid + 8 * (reg >> 1);
            vals[reg * 2 + 0] = __float2half_rn(sx[row * BK + k]);
            vals[reg * 2 + 1] = __float2half_rn(sx[row * BK + k + 1]);
        }
        *(uint4*)(dst + h0) = *(const uint4*)vals;
    }
}

// ------------------------------------------------------------- GEMM (R16 core)
extern __shared__ __align__(128) char dsmem[];

__global__ __launch_bounds__(THREADS, 3)
void gemm_kernel(float* __restrict__ out)
{
    const int tid  = threadIdx.x;
    const int warp = tid >> 5;
    const int lane = tid & 31;
    const int grp  = lane >> 2;
    const int qid  = lane & 3;
    const int rb0  = (warp >> 1) * 4;        // A block base (64 rows)
    const int nb0  = (warp & 1) * 8;         // B block base (64 cols)
    const int pb0  = nb0 >> 1;               // B pair base (4 pairs)
    const int blockN = blockIdx.x * BN;
    const int mt     = blockIdx.y;
    const int blockM = mt * BM;

    const int nv = g_cv;
    const char* gA = (const char*)(g_x + (size_t)mt * NK * PANEL_H);
    const char* gB = (const char*)(((blockM < nv) ? g_wv : g_wt)
                                   + (size_t)blockIdx.x * NK * PANEL_H);

    const uint32_t sbase = smem_u32(dsmem);

    float acc[4][8][4];
    #pragma unroll
    for (int i = 0; i < 4; i++)
        #pragma unroll
        for (int j = 0; j < 8; j++)
            #pragma unroll
            for (int c = 0; c < 4; c++) acc[i][j][c] = 0.f;

    auto ISSUE = [&](int kt) {
        const uint32_t sst = sbase + (kt & (STAGES - 1)) * STAGE_B;
        const char* srcA = gA + (size_t)kt * APANEL_B;
        const char* srcB = gB + (size_t)kt * APANEL_B;
        #pragma unroll
        for (int i = 0; i < 4; i++) {
            uint32_t off = (uint32_t)(i * 2048 + tid * 16);
            cp16(sst + off, srcA + off);
        }
        #pragma unroll
        for (int i = 0; i < 4; i++) {
            uint32_t off = (uint32_t)(i * 2048 + tid * 16);
            cp16(sst + APANEL_B + off, srcB + off);
        }
        asm volatile("cp.async.commit_group;" ::: "memory");
    };

    ISSUE(0); ISSUE(1); ISSUE(2);

    for (int kt = 0; kt < NK; kt++) {
        // Tail-correct wait: group kt must be complete past this point.
        if (kt < NK - 2)
            asm volatile("cp.async.wait_group 2;" ::: "memory");
        else if (kt == NK - 2)
            asm volatile("cp.async.wait_group 1;" ::: "memory");
        else
            asm volatile("cp.async.wait_group 0;" ::: "memory");
        __syncthreads();
        if (kt + STAGES - 1 < NK) ISSUE(kt + STAGES - 1);

        const char* stage = dsmem + (kt & (STAGES - 1)) * STAGE_B;
        const char* sB = stage + APANEL_B;

        #pragma unroll
        for (int ks = 0; ks < 2; ks++) {
            uint32_t a[4][4];
            #pragma unroll
            for (int i = 0; i < 4; i++) {
                uint4 v = *(const uint4*)(stage + ((rb0 + i) * 2 + ks) * 512
                                          + lane * 16);
                a[i][0] = v.x; a[i][1] = v.y; a[i][2] = v.z; a[i][3] = v.w;
            }
            uint32_t b[8][2];
            #pragma unroll
            for (int jp = 0; jp < 4; jp++) {
                uint4 v = *(const uint4*)(sB + ((pb0 + jp) * 2 + ks) * 512
                                          + lane * 16);
                b[2 * jp][0] = v.x;     b[2 * jp][1] = v.y;
                b[2 * jp + 1][0] = v.z; b[2 * jp + 1][1] = v.w;
            }
            #pragma unroll
            for (int i = 0; i < 4; i++)
                #pragma unroll
                for (int j = 0; j < 8; j++)
                    mma_f16(acc[i][j], a[i], b[j]);
        }
    }

    // epilogue: scatter live rows through perm
    #pragma unroll
    for (int i = 0; i < 4; i++) {
        int r = (rb0 + i) * 16 + grp;
        int s0 = blockM + r, s1 = blockM + r + 8;
        int d0 = ((s0 < nv) || (s0 >= nv + BM)) ? g_perm[s0] : -1;
        int d1 = ((s1 < nv) || (s1 >= nv + BM)) ? g_perm[s1] : -1;
        #pragma unroll
        for (int j = 0; j < 8; j++) {
            int col = blockN + (nb0 + j) * 8 + qid * 2;
            if (d0 >= 0)
                *(float2*)(out + (size_t)d0 * N_DIM + col) =
                    make_float2(acc[i][j][0], acc[i][j][1]);
            if (d1 >= 0)
                *(float2*)(out + (size_t)d1 * N_DIM + col) =
                    make_float2(acc[i][j][2], acc[i][j][3]);
        }
    }
}

// ------------------------------------------------------------- launch
extern "C" void kernel_launch(void* const* d_in, const int* in_sizes, int n_in,
                              void* d_out, int out_size)
{
    const float*         x    = (const float*)d_in[0];
    const unsigned char* mask = (const unsigned char*)d_in[1];
    const float*         Wv   = (const float*)d_in[2];
    const float*         Wt   = (const float*)d_in[3];
    float*               out  = (float*)d_out;

    static bool attr_set = false;
    if (!attr_set) {
        cudaFuncSetAttribute(gemm_kernel,
                             cudaFuncAttributeMaxDynamicSharedMemorySize, DYN_SMEM);
        attr_set = true;
    }

    // zero the slot counters (graph-capturable, no allocation)
    int* cv_addr = nullptr;
    cudaGetSymbolAddress((void**)&cv_addr, g_cv);
    cudaMemsetAsync(cv_addr, 0, sizeof(int));
    int* ct_addr = nullptr;
    cudaGetSymbolAddress((void**)&ct_addr, g_ct);
    cudaMemsetAsync(ct_addr, 0, sizeof(int));

    k12_assign_w<<<MASK_BLOCKS + W_BLOCKS, 256>>>(mask, Wv, Wt);
    k34_xconv<<<dim3(NMT, NK), 256>>>(x);
    gemm_kernel<<<dim3(N_DIM / BN, NMT), THREADS, DYN_SMEM>>>(out);
}